// round 1
// baseline (speedup 1.0000x reference)
#include <cuda_runtime.h>
#include <cuda_bf16.h>

// Problem constants (fixed shapes from reference)
#define BATCH 8
#define SDIM  32
#define NTOK  1024          // S*S
#define CH    512
#define NHEAD 16
#define HD    32
#define SCALE 0.17677669529663689f   // 1/sqrt(32)

// Scratch: q,k,v,attn_out in (B, h, N, d) layout. 16 MB each.
__device__ float g_q[BATCH * NHEAD * NTOK * HD];
__device__ float g_k[BATCH * NHEAD * NTOK * HD];
__device__ float g_v[BATCH * NHEAD * NTOK * HD];
__device__ float g_o[BATCH * NHEAD * NTOK * HD];

// ---------------------------------------------------------------------------
// Kernel 1: QKV GEMM.  X(8192,512) @ W^T(512,1536) + b  ->  split q/k/v
// 64x64 tile, 16-deep K slices, 256 threads, 4x4 micro-tile per thread.
// ---------------------------------------------------------------------------
__global__ void qkv_gemm(const float* __restrict__ X,
                         const float* __restrict__ W,
                         const float* __restrict__ bias)
{
    const int K = CH;
    __shared__ float As[16][68];
    __shared__ float Bs[16][68];

    const int tid = threadIdx.x;
    const int tx  = tid & 15;
    const int ty  = tid >> 4;
    const int m0  = blockIdx.y * 64;
    const int n0  = blockIdx.x * 64;

    float acc[4][4];
#pragma unroll
    for (int i = 0; i < 4; i++)
#pragma unroll
        for (int j = 0; j < 4; j++) acc[i][j] = 0.f;

    for (int k0 = 0; k0 < K; k0 += 16) {
#pragma unroll
        for (int e = tid; e < 1024; e += 256) {
            int kk = e & 15, r = e >> 4;
            As[kk][r] = X[(size_t)(m0 + r) * K + k0 + kk];
            Bs[kk][r] = W[(size_t)(n0 + r) * K + k0 + kk];
        }
        __syncthreads();
#pragma unroll
        for (int kk = 0; kk < 16; kk++) {
            float4 a4 = *(const float4*)&As[kk][ty * 4];
            float4 b4 = *(const float4*)&Bs[kk][tx * 4];
            float a[4] = {a4.x, a4.y, a4.z, a4.w};
            float b[4] = {b4.x, b4.y, b4.z, b4.w};
#pragma unroll
            for (int i = 0; i < 4; i++)
#pragma unroll
                for (int j = 0; j < 4; j++) acc[i][j] += a[i] * b[j];
        }
        __syncthreads();
    }

#pragma unroll
    for (int i = 0; i < 4; i++) {
        int m = m0 + ty * 4 + i;
        int b = m >> 10;           // /1024
        int n = m & 1023;
#pragma unroll
        for (int j = 0; j < 4; j++) {
            int jj  = n0 + tx * 4 + j;
            float v = acc[i][j] + bias[jj];
            int which = jj >> 9;            // /512
            int h     = (jj >> 5) & 15;
            int dd    = jj & 31;
            size_t off = ((size_t)(b * NHEAD + h) * NTOK + n) * HD + dd;
            if (which == 0)      g_q[off] = v * SCALE;
            else if (which == 1) g_k[off] = v;
            else                 g_v[off] = v;
        }
    }
}

// ---------------------------------------------------------------------------
// Kernel 2: fused attention with analytic relative-position-bias gather.
// bias[h][i][j] = rpb[h][(jh-ih+31)*63 + (jw-iw+31)]  (flip-flip collapses to
// negated relative offset). One query row per thread, 32-row K/V smem tiles,
// online softmax.
// ---------------------------------------------------------------------------
__global__ void attn_kernel(const float* __restrict__ rpb)
{
    const int bh = blockIdx.x;              // b*16 + h
    const int h  = bh & 15;
    const int i  = blockIdx.y * 128 + threadIdx.x;   // query row

    const float* qp = g_q + ((size_t)bh * NTOK + i) * HD;
    float qr[32];
#pragma unroll
    for (int c4 = 0; c4 < 8; c4++) {
        float4 t = *(const float4*)(qp + c4 * 4);
        qr[c4*4+0] = t.x; qr[c4*4+1] = t.y; qr[c4*4+2] = t.z; qr[c4*4+3] = t.w;
    }

    __shared__ float Ks[32][32];
    __shared__ float Vs[32][32];

    const float* rpbh = rpb + (size_t)h * 63 * 63;
    const int ih = i >> 5, iw = i & 31;

    float m = -1e30f, l = 0.f;
    float o[32];
#pragma unroll
    for (int c = 0; c < 32; c++) o[c] = 0.f;

    for (int t = 0; t < 32; t++) {
        size_t base = ((size_t)bh * NTOK + t * 32) * HD;
        for (int e = threadIdx.x; e < 1024; e += 128) {
            (&Ks[0][0])[e] = g_k[base + e];
            (&Vs[0][0])[e] = g_v[base + e];
        }
        __syncthreads();

        float s[32];
        float tmax = -1e30f;
#pragma unroll
        for (int j = 0; j < 32; j++) {
            float dot = 0.f;
            const float4* K4 = (const float4*)Ks[j];
#pragma unroll
            for (int c4 = 0; c4 < 8; c4++) {
                float4 kv = K4[c4];
                dot += qr[c4*4+0]*kv.x + qr[c4*4+1]*kv.y
                     + qr[c4*4+2]*kv.z + qr[c4*4+3]*kv.w;
            }
            int jg = t * 32 + j;
            int jh = jg >> 5, jw = jg & 31;
            dot += __ldg(&rpbh[(jh - ih + 31) * 63 + (jw - iw + 31)]);
            s[j] = dot;
            tmax = fmaxf(tmax, dot);
        }

        float mnew = fmaxf(m, tmax);
        float corr = __expf(m - mnew);
        l *= corr;
#pragma unroll
        for (int c = 0; c < 32; c++) o[c] *= corr;

#pragma unroll
        for (int j = 0; j < 32; j++) {
            float p = __expf(s[j] - mnew);
            l += p;
            const float4* V4 = (const float4*)Vs[j];
#pragma unroll
            for (int c4 = 0; c4 < 8; c4++) {
                float4 vv = V4[c4];
                o[c4*4+0] += p * vv.x; o[c4*4+1] += p * vv.y;
                o[c4*4+2] += p * vv.z; o[c4*4+3] += p * vv.w;
            }
        }
        m = mnew;
        __syncthreads();
    }

    float inv = 1.f / l;
    float* op = g_o + ((size_t)bh * NTOK + i) * HD;
#pragma unroll
    for (int c4 = 0; c4 < 8; c4++) {
        float4 t4 = make_float4(o[c4*4+0]*inv, o[c4*4+1]*inv,
                                o[c4*4+2]*inv, o[c4*4+3]*inv);
        *(float4*)(op + c4 * 4) = t4;
    }
}

// ---------------------------------------------------------------------------
// Kernel 3: output projection.  Gathers (B,h,N,d) -> (B,N,C) inside A-tile
// load, then (8192,512) @ proj_w^T(512,512) + b -> d_out.
// ---------------------------------------------------------------------------
__global__ void proj_gemm(const float* __restrict__ W,
                          const float* __restrict__ bias,
                          float* __restrict__ out)
{
    const int K = CH;
    __shared__ float As[16][68];
    __shared__ float Bs[16][68];

    const int tid = threadIdx.x;
    const int tx  = tid & 15;
    const int ty  = tid >> 4;
    const int m0  = blockIdx.y * 64;
    const int n0  = blockIdx.x * 64;

    float acc[4][4];
#pragma unroll
    for (int i = 0; i < 4; i++)
#pragma unroll
        for (int j = 0; j < 4; j++) acc[i][j] = 0.f;

    for (int k0 = 0; k0 < K; k0 += 16) {
#pragma unroll
        for (int e = tid; e < 1024; e += 256) {
            int kk = e & 15, r = e >> 4;
            int m = m0 + r;
            int k = k0 + kk;
            int b = m >> 10, n = m & 1023;
            As[kk][r] = g_o[((size_t)(b * NHEAD + (k >> 5)) * NTOK + n) * HD + (k & 31)];
            Bs[kk][r] = W[(size_t)(n0 + r) * K + k];
        }
        __syncthreads();
#pragma unroll
        for (int kk = 0; kk < 16; kk++) {
            float4 a4 = *(const float4*)&As[kk][ty * 4];
            float4 b4 = *(const float4*)&Bs[kk][tx * 4];
            float a[4] = {a4.x, a4.y, a4.z, a4.w};
            float b[4] = {b4.x, b4.y, b4.z, b4.w};
#pragma unroll
            for (int i = 0; i < 4; i++)
#pragma unroll
                for (int j = 0; j < 4; j++) acc[i][j] += a[i] * b[j];
        }
        __syncthreads();
    }

#pragma unroll
    for (int i = 0; i < 4; i++) {
        int m = m0 + ty * 4 + i;
#pragma unroll
        for (int j = 0; j < 4; j++) {
            int jj = n0 + tx * 4 + j;
            out[(size_t)m * CH + jj] = acc[i][j] + bias[jj];
        }
    }
}

// ---------------------------------------------------------------------------
extern "C" void kernel_launch(void* const* d_in, const int* in_sizes, int n_in,
                              void* d_out, int out_size)
{
    const float* x      = (const float*)d_in[0];
    const float* qkv_w  = (const float*)d_in[1];
    const float* qkv_b  = (const float*)d_in[2];
    const float* rpb    = (const float*)d_in[3];
    const float* proj_w = (const float*)d_in[4];
    const float* proj_b = (const float*)d_in[5];
    float* out = (float*)d_out;

    // QKV: M=8192, N=1536 -> grid (1536/64, 8192/64)
    qkv_gemm<<<dim3(24, 128), 256>>>(x, qkv_w, qkv_b);

    // Attention: (b*h, query-tile of 128) x 128 threads
    attn_kernel<<<dim3(BATCH * NHEAD, NTOK / 128), 128>>>(rpb);

    // Proj: M=8192, N=512 -> grid (512/64, 8192/64)
    proj_gemm<<<dim3(8, 128), 256>>>(proj_w, proj_b, out);
}

// round 2
// speedup vs baseline: 6.0263x; 6.0263x over previous
#include <cuda_runtime.h>
#include <cuda_fp16.h>
#include <cstdint>

#define BATCH 8
#define NTOK  1024
#define CH    512
#define NHEAD 16
#define HD    32
#define SCALE 0.17677669529663689f

// fp16 scratch: q,k,v in (B,h,N,d); attention output in (B,N,C)
__device__ __half g_q[BATCH * NHEAD * NTOK * HD];
__device__ __half g_k[BATCH * NHEAD * NTOK * HD];
__device__ __half g_v[BATCH * NHEAD * NTOK * HD];
__device__ __half g_oh[BATCH * NTOK * CH];

__device__ __forceinline__ uint32_t smem_u32(const void* p) {
    return (uint32_t)__cvta_generic_to_shared(p);
}
__device__ __forceinline__ void ldm_x4(uint32_t* r, uint32_t a) {
    asm volatile("ldmatrix.sync.aligned.m8n8.x4.shared.b16 {%0,%1,%2,%3}, [%4];"
                 : "=r"(r[0]), "=r"(r[1]), "=r"(r[2]), "=r"(r[3]) : "r"(a));
}
__device__ __forceinline__ void ldm_x4_t(uint32_t* r, uint32_t a) {
    asm volatile("ldmatrix.sync.aligned.m8n8.x4.trans.shared.b16 {%0,%1,%2,%3}, [%4];"
                 : "=r"(r[0]), "=r"(r[1]), "=r"(r[2]), "=r"(r[3]) : "r"(a));
}
__device__ __forceinline__ void mma16816(float* c, const uint32_t* a, const uint32_t* b) {
    asm volatile(
        "mma.sync.aligned.m16n8k16.row.col.f32.f16.f16.f32 "
        "{%0,%1,%2,%3}, {%4,%5,%6,%7}, {%8,%9}, {%0,%1,%2,%3};"
        : "+f"(c[0]), "+f"(c[1]), "+f"(c[2]), "+f"(c[3])
        : "r"(a[0]), "r"(a[1]), "r"(a[2]), "r"(a[3]), "r"(b[0]), "r"(b[1]));
}
__device__ __forceinline__ uint32_t pack_h2(float x, float y) {
    __half2 h = __floats2half2_rn(x, y);
    return *(uint32_t*)&h;
}

// ---------------------------------------------------------------------------
// Kernel 1: QKV GEMM (fp16 mma).  X(8192,512) @ W^T -> q/k/v fp16 scratch.
// ---------------------------------------------------------------------------
__global__ __launch_bounds__(256) void qkv_gemm(const float* __restrict__ X,
                                                const float* __restrict__ W,
                                                const float* __restrict__ bias)
{
    __shared__ __align__(16) __half As[128][40];
    __shared__ __align__(16) __half Bs[128][40];

    const int tid = threadIdx.x, lane = tid & 31, w = tid >> 5;
    const int wm = w >> 1, wn = w & 1;
    const int m0 = blockIdx.y * 128, n0 = blockIdx.x * 128;

    float acc[2][8][4];
#pragma unroll
    for (int mt = 0; mt < 2; mt++)
#pragma unroll
        for (int nt = 0; nt < 8; nt++)
#pragma unroll
            for (int c = 0; c < 4; c++) acc[mt][nt][c] = 0.f;

    // ldmatrix source addresses (constant across k-loop except column shift)
    const int a_row = wm * 32 + (lane & 15);
    const int a_colb = (lane >> 4) * 8;
    const int b_rowb = wn * 64 + (lane & 7) + ((lane >> 4) << 3);
    const int b_colb = ((lane >> 3) & 1) * 8;

    for (int k0 = 0; k0 < CH; k0 += 32) {
#pragma unroll
        for (int i = 0; i < 4; i++) {
            int e = tid + i * 256;
            int row = e >> 3, c4 = e & 7;
            float4 xa = __ldg((const float4*)(X + (size_t)(m0 + row) * CH + k0 + c4 * 4));
            *(__half2*)&As[row][c4 * 4]     = __floats2half2_rn(xa.x, xa.y);
            *(__half2*)&As[row][c4 * 4 + 2] = __floats2half2_rn(xa.z, xa.w);
            float4 wb = __ldg((const float4*)(W + (size_t)(n0 + row) * CH + k0 + c4 * 4));
            *(__half2*)&Bs[row][c4 * 4]     = __floats2half2_rn(wb.x, wb.y);
            *(__half2*)&Bs[row][c4 * 4 + 2] = __floats2half2_rn(wb.z, wb.w);
        }
        __syncthreads();

#pragma unroll
        for (int ks = 0; ks < 2; ks++) {
            uint32_t aF[2][4];
#pragma unroll
            for (int mt = 0; mt < 2; mt++)
                ldm_x4(aF[mt], smem_u32(&As[a_row + mt * 16][ks * 16 + a_colb]));
            uint32_t bF[8][2];
#pragma unroll
            for (int q = 0; q < 4; q++) {
                uint32_t r[4];
                ldm_x4(r, smem_u32(&Bs[b_rowb + q * 16][ks * 16 + b_colb]));
                bF[2 * q][0] = r[0]; bF[2 * q][1] = r[1];
                bF[2 * q + 1][0] = r[2]; bF[2 * q + 1][1] = r[3];
            }
#pragma unroll
            for (int mt = 0; mt < 2; mt++)
#pragma unroll
                for (int nt = 0; nt < 8; nt++)
                    mma16816(acc[mt][nt], aF[mt], bF[nt]);
        }
        __syncthreads();
    }

    const int qr = lane >> 2, qc = (lane & 3) * 2;
#pragma unroll
    for (int mt = 0; mt < 2; mt++) {
#pragma unroll
        for (int nt = 0; nt < 8; nt++) {
            int jj = n0 + wn * 64 + nt * 8 + qc;
            float b0 = __ldg(&bias[jj]), b1 = __ldg(&bias[jj + 1]);
            int which = jj >> 9, h = (jj >> 5) & 15, dd = jj & 31;
#pragma unroll
            for (int rr = 0; rr < 2; rr++) {
                int m = m0 + wm * 32 + mt * 16 + qr + rr * 8;
                int b = m >> 10, n = m & 1023;
                float v0 = acc[mt][nt][rr * 2 + 0] + b0;
                float v1 = acc[mt][nt][rr * 2 + 1] + b1;
                if (which == 0) { v0 *= SCALE; v1 *= SCALE; }
                __half2 hv = __floats2half2_rn(v0, v1);
                size_t off = ((size_t)(b * NHEAD + h) * NTOK + n) * HD + dd;
                if (which == 0)      *(__half2*)&g_q[off] = hv;
                else if (which == 1) *(__half2*)&g_k[off] = hv;
                else                 *(__half2*)&g_v[off] = hv;
            }
        }
    }
}

// ---------------------------------------------------------------------------
// Kernel 2: flash attention, all-tensor, analytic RPB from smem.
// Block: 4 warps, 64 query rows, loops over 16 key tiles of 64.
// ---------------------------------------------------------------------------
__global__ __launch_bounds__(128) void attn_kernel(const float* __restrict__ rpb)
{
    const int bh = blockIdx.x;
    const int b  = bh >> 4, h = bh & 15;
    const int qbase = blockIdx.y * 64;
    const int tid = threadIdx.x, lane = tid & 31, w = tid >> 5;

    __shared__ float rpb_s[3969];
    __shared__ __align__(16) __half Qs[64][40];
    __shared__ __align__(16) __half Ks[64][40];
    __shared__ __align__(16) __half Vs[64][40];

    for (int e = tid; e < 3969; e += 128)
        rpb_s[e] = __ldg(rpb + (size_t)h * 3969 + e);

    const __half* qg = g_q + ((size_t)bh * NTOK + qbase) * HD;
#pragma unroll
    for (int i = 0; i < 2; i++) {
        int e = tid + i * 128;
        int row = e >> 2, c8 = e & 3;
        *(uint4*)&Qs[row][c8 * 8] = *(const uint4*)(qg + row * HD + c8 * 8);
    }
    __syncthreads();

    uint32_t aQ[2][4];
#pragma unroll
    for (int ks = 0; ks < 2; ks++)
        ldm_x4(aQ[ks], smem_u32(&Qs[w * 16 + (lane & 15)][ks * 16 + (lane >> 4) * 8]));

    const int qr = lane >> 2, qc = (lane & 3) * 2;
    const int i1 = qbase + w * 16 + qr, i2 = i1 + 8;
    const int off1 = (31 - (i1 >> 5)) * 63 + (31 - (i1 & 31));
    const int off2 = (31 - (i2 >> 5)) * 63 + (31 - (i2 & 31));

    float m1 = -1e30f, m2 = -1e30f, l1 = 0.f, l2 = 0.f;
    float oacc[4][4];
#pragma unroll
    for (int i = 0; i < 4; i++)
#pragma unroll
        for (int c = 0; c < 4; c++) oacc[i][c] = 0.f;

    const int kb_row = (lane & 7) + ((lane >> 4) << 3);
    const int kb_col = ((lane >> 3) & 1) * 8;

    for (int kt = 0; kt < 16; kt++) {
        const __half* kg = g_k + ((size_t)bh * NTOK + kt * 64) * HD;
        const __half* vg = g_v + ((size_t)bh * NTOK + kt * 64) * HD;
#pragma unroll
        for (int i = 0; i < 2; i++) {
            int e = tid + i * 128;
            int row = e >> 2, c8 = e & 3;
            *(uint4*)&Ks[row][c8 * 8] = *(const uint4*)(kg + row * HD + c8 * 8);
            *(uint4*)&Vs[row][c8 * 8] = *(const uint4*)(vg + row * HD + c8 * 8);
        }
        __syncthreads();

        float sc[8][4];
#pragma unroll
        for (int nt = 0; nt < 8; nt++)
#pragma unroll
            for (int c = 0; c < 4; c++) sc[nt][c] = 0.f;

#pragma unroll
        for (int ks = 0; ks < 2; ks++) {
#pragma unroll
            for (int q = 0; q < 4; q++) {
                uint32_t r[4];
                ldm_x4(r, smem_u32(&Ks[q * 16 + kb_row][ks * 16 + kb_col]));
                uint32_t b0[2] = { r[0], r[1] }, b1[2] = { r[2], r[3] };
                mma16816(sc[2 * q],     aQ[ks], b0);
                mma16816(sc[2 * q + 1], aQ[ks], b1);
            }
        }

        // bias + online softmax
        float tm1 = -1e30f, tm2 = -1e30f;
#pragma unroll
        for (int nt = 0; nt < 8; nt++) {
            int j0 = kt * 64 + nt * 8 + qc;
            int ja = j0 + 31 * (j0 >> 5);
            sc[nt][0] += rpb_s[off1 + ja];
            sc[nt][1] += rpb_s[off1 + ja + 1];
            sc[nt][2] += rpb_s[off2 + ja];
            sc[nt][3] += rpb_s[off2 + ja + 1];
            tm1 = fmaxf(tm1, fmaxf(sc[nt][0], sc[nt][1]));
            tm2 = fmaxf(tm2, fmaxf(sc[nt][2], sc[nt][3]));
        }
        tm1 = fmaxf(tm1, __shfl_xor_sync(0xffffffffu, tm1, 1));
        tm1 = fmaxf(tm1, __shfl_xor_sync(0xffffffffu, tm1, 2));
        tm2 = fmaxf(tm2, __shfl_xor_sync(0xffffffffu, tm2, 1));
        tm2 = fmaxf(tm2, __shfl_xor_sync(0xffffffffu, tm2, 2));

        float mn1 = fmaxf(m1, tm1), mn2 = fmaxf(m2, tm2);
        float cr1 = __expf(m1 - mn1), cr2 = __expf(m2 - mn2);
        l1 *= cr1; l2 *= cr2;
#pragma unroll
        for (int ntd = 0; ntd < 4; ntd++) {
            oacc[ntd][0] *= cr1; oacc[ntd][1] *= cr1;
            oacc[ntd][2] *= cr2; oacc[ntd][3] *= cr2;
        }
        float rs1 = 0.f, rs2 = 0.f;
#pragma unroll
        for (int nt = 0; nt < 8; nt++) {
            sc[nt][0] = __expf(sc[nt][0] - mn1); rs1 += sc[nt][0];
            sc[nt][1] = __expf(sc[nt][1] - mn1); rs1 += sc[nt][1];
            sc[nt][2] = __expf(sc[nt][2] - mn2); rs2 += sc[nt][2];
            sc[nt][3] = __expf(sc[nt][3] - mn2); rs2 += sc[nt][3];
        }
        rs1 += __shfl_xor_sync(0xffffffffu, rs1, 1);
        rs1 += __shfl_xor_sync(0xffffffffu, rs1, 2);
        rs2 += __shfl_xor_sync(0xffffffffu, rs2, 1);
        rs2 += __shfl_xor_sync(0xffffffffu, rs2, 2);
        l1 += rs1; l2 += rs2;
        m1 = mn1; m2 = mn2;

        // P @ V
#pragma unroll
        for (int kk = 0; kk < 4; kk++) {
            uint32_t aP[4];
            aP[0] = pack_h2(sc[2 * kk][0],     sc[2 * kk][1]);
            aP[1] = pack_h2(sc[2 * kk][2],     sc[2 * kk][3]);
            aP[2] = pack_h2(sc[2 * kk + 1][0], sc[2 * kk + 1][1]);
            aP[3] = pack_h2(sc[2 * kk + 1][2], sc[2 * kk + 1][3]);
#pragma unroll
            for (int dp = 0; dp < 2; dp++) {
                uint32_t r[4];
                ldm_x4_t(r, smem_u32(&Vs[kk * 16 + (lane & 15)][dp * 16 + (lane >> 4) * 8]));
                uint32_t b0[2] = { r[0], r[1] }, b1[2] = { r[2], r[3] };
                mma16816(oacc[2 * dp],     aP, b0);
                mma16816(oacc[2 * dp + 1], aP, b1);
            }
        }
        __syncthreads();
    }

    float inv1 = 1.f / l1, inv2 = 1.f / l2;
#pragma unroll
    for (int ntd = 0; ntd < 4; ntd++) {
        int d0 = ntd * 8 + qc;
        *(__half2*)&g_oh[((size_t)b * NTOK + i1) * CH + h * HD + d0] =
            __floats2half2_rn(oacc[ntd][0] * inv1, oacc[ntd][1] * inv1);
        *(__half2*)&g_oh[((size_t)b * NTOK + i2) * CH + h * HD + d0] =
            __floats2half2_rn(oacc[ntd][2] * inv2, oacc[ntd][3] * inv2);
    }
}

// ---------------------------------------------------------------------------
// Kernel 3: projection GEMM (fp16 mma). A = g_oh fp16 (B,N,C) direct.
// ---------------------------------------------------------------------------
__global__ __launch_bounds__(256) void proj_gemm(const float* __restrict__ W,
                                                 const float* __restrict__ bias,
                                                 float* __restrict__ out)
{
    __shared__ __align__(16) __half As[128][40];
    __shared__ __align__(16) __half Bs[128][40];

    const int tid = threadIdx.x, lane = tid & 31, w = tid >> 5;
    const int wm = w >> 1, wn = w & 1;
    const int m0 = blockIdx.y * 128, n0 = blockIdx.x * 128;

    float acc[2][8][4];
#pragma unroll
    for (int mt = 0; mt < 2; mt++)
#pragma unroll
        for (int nt = 0; nt < 8; nt++)
#pragma unroll
            for (int c = 0; c < 4; c++) acc[mt][nt][c] = 0.f;

    const int a_row = wm * 32 + (lane & 15);
    const int a_colb = (lane >> 4) * 8;
    const int b_rowb = wn * 64 + (lane & 7) + ((lane >> 4) << 3);
    const int b_colb = ((lane >> 3) & 1) * 8;

    for (int k0 = 0; k0 < CH; k0 += 32) {
        // A: fp16 direct copy
#pragma unroll
        for (int i = 0; i < 2; i++) {
            int e = tid + i * 256;
            int row = e >> 2, c8 = e & 3;
            *(uint4*)&As[row][c8 * 8] =
                *(const uint4*)(g_oh + (size_t)(m0 + row) * CH + k0 + c8 * 8);
        }
        // B: fp32 -> fp16 convert
#pragma unroll
        for (int i = 0; i < 4; i++) {
            int e = tid + i * 256;
            int row = e >> 3, c4 = e & 7;
            float4 wb = __ldg((const float4*)(W + (size_t)(n0 + row) * CH + k0 + c4 * 4));
            *(__half2*)&Bs[row][c4 * 4]     = __floats2half2_rn(wb.x, wb.y);
            *(__half2*)&Bs[row][c4 * 4 + 2] = __floats2half2_rn(wb.z, wb.w);
        }
        __syncthreads();

#pragma unroll
        for (int ks = 0; ks < 2; ks++) {
            uint32_t aF[2][4];
#pragma unroll
            for (int mt = 0; mt < 2; mt++)
                ldm_x4(aF[mt], smem_u32(&As[a_row + mt * 16][ks * 16 + a_colb]));
            uint32_t bF[8][2];
#pragma unroll
            for (int q = 0; q < 4; q++) {
                uint32_t r[4];
                ldm_x4(r, smem_u32(&Bs[b_rowb + q * 16][ks * 16 + b_colb]));
                bF[2 * q][0] = r[0]; bF[2 * q][1] = r[1];
                bF[2 * q + 1][0] = r[2]; bF[2 * q + 1][1] = r[3];
            }
#pragma unroll
            for (int mt = 0; mt < 2; mt++)
#pragma unroll
                for (int nt = 0; nt < 8; nt++)
                    mma16816(acc[mt][nt], aF[mt], bF[nt]);
        }
        __syncthreads();
    }

    const int qr = lane >> 2, qc = (lane & 3) * 2;
#pragma unroll
    for (int mt = 0; mt < 2; mt++) {
#pragma unroll
        for (int nt = 0; nt < 8; nt++) {
            int jj = n0 + wn * 64 + nt * 8 + qc;
            float b0 = __ldg(&bias[jj]), b1 = __ldg(&bias[jj + 1]);
#pragma unroll
            for (int rr = 0; rr < 2; rr++) {
                int m = m0 + wm * 32 + mt * 16 + qr + rr * 8;
                float2 v = make_float2(acc[mt][nt][rr * 2 + 0] + b0,
                                       acc[mt][nt][rr * 2 + 1] + b1);
                *(float2*)&out[(size_t)m * CH + jj] = v;
            }
        }
    }
}

// ---------------------------------------------------------------------------
extern "C" void kernel_launch(void* const* d_in, const int* in_sizes, int n_in,
                              void* d_out, int out_size)
{
    const float* x      = (const float*)d_in[0];
    const float* qkv_w  = (const float*)d_in[1];
    const float* qkv_b  = (const float*)d_in[2];
    const float* rpb    = (const float*)d_in[3];
    const float* proj_w = (const float*)d_in[4];
    const float* proj_b = (const float*)d_in[5];
    float* out = (float*)d_out;

    qkv_gemm<<<dim3(12, 64), 256>>>(x, qkv_w, qkv_b);
    attn_kernel<<<dim3(BATCH * NHEAD, NTOK / 64), 128>>>(rpb);
    proj_gemm<<<dim3(4, 64), 256>>>(proj_w, proj_b, out);
}

// round 3
// speedup vs baseline: 6.6030x; 1.0957x over previous
#include <cuda_runtime.h>
#include <cuda_fp16.h>
#include <cstdint>

#define BATCH 8
#define NTOK  1024
#define CH    512
#define NHEAD 16
#define HD    32
#define SCALE 0.17677669529663689f

// fp16 scratch
__device__ __half g_xh[BATCH * NTOK * CH];          // converted input X
__device__ __half g_wqh[3 * CH * CH];               // converted qkv_w
__device__ __half g_pwh[CH * CH];                   // converted proj_w
__device__ __half g_q[BATCH * NHEAD * NTOK * HD];
__device__ __half g_k[BATCH * NHEAD * NTOK * HD];
__device__ __half g_v[BATCH * NHEAD * NTOK * HD];
__device__ __half g_oh[BATCH * NTOK * CH];          // attn out, (B,N,C)

__device__ __forceinline__ uint32_t smem_u32(const void* p) {
    return (uint32_t)__cvta_generic_to_shared(p);
}
__device__ __forceinline__ void cp16(void* sdst, const void* gsrc) {
    asm volatile("cp.async.cg.shared.global [%0], [%1], 16;"
                 :: "r"(smem_u32(sdst)), "l"(gsrc));
}
#define CP_COMMIT() asm volatile("cp.async.commit_group;" ::: "memory")
#define CP_WAIT0()  asm volatile("cp.async.wait_group 0;" ::: "memory")
#define CP_WAIT1()  asm volatile("cp.async.wait_group 1;" ::: "memory")

__device__ __forceinline__ void ldm_x4(uint32_t* r, uint32_t a) {
    asm volatile("ldmatrix.sync.aligned.m8n8.x4.shared.b16 {%0,%1,%2,%3}, [%4];"
                 : "=r"(r[0]), "=r"(r[1]), "=r"(r[2]), "=r"(r[3]) : "r"(a));
}
__device__ __forceinline__ void ldm_x4_t(uint32_t* r, uint32_t a) {
    asm volatile("ldmatrix.sync.aligned.m8n8.x4.trans.shared.b16 {%0,%1,%2,%3}, [%4];"
                 : "=r"(r[0]), "=r"(r[1]), "=r"(r[2]), "=r"(r[3]) : "r"(a));
}
__device__ __forceinline__ void mma16816(float* c, const uint32_t* a, const uint32_t* b) {
    asm volatile(
        "mma.sync.aligned.m16n8k16.row.col.f32.f16.f16.f32 "
        "{%0,%1,%2,%3}, {%4,%5,%6,%7}, {%8,%9}, {%0,%1,%2,%3};"
        : "+f"(c[0]), "+f"(c[1]), "+f"(c[2]), "+f"(c[3])
        : "r"(a[0]), "r"(a[1]), "r"(a[2]), "r"(a[3]), "r"(b[0]), "r"(b[1]));
}
__device__ __forceinline__ uint32_t pack_h2(float x, float y) {
    __half2 h = __floats2half2_rn(x, y);
    return *(uint32_t*)&h;
}

// ---------------------------------------------------------------------------
// Kernel 0: one-shot fp32 -> fp16 conversion of X, qkv_w, proj_w.
// ---------------------------------------------------------------------------
#define NX4  (BATCH * NTOK * CH / 4)     // 1048576
#define NWQ4 (3 * CH * CH / 4)           // 196608
#define NWP4 (CH * CH / 4)               // 65536

__global__ __launch_bounds__(256) void convert_all(const float4* __restrict__ X,
                                                   const float4* __restrict__ Wq,
                                                   const float4* __restrict__ Wp)
{
    int i = blockIdx.x * 256 + threadIdx.x;
    const float4* src;
    __half2* dst;
    int j;
    if (i < NX4)              { src = X;  dst = (__half2*)g_xh;  j = i; }
    else if (i < NX4 + NWQ4)  { src = Wq; dst = (__half2*)g_wqh; j = i - NX4; }
    else if (i < NX4 + NWQ4 + NWP4) { src = Wp; dst = (__half2*)g_pwh; j = i - NX4 - NWQ4; }
    else return;
    float4 v = __ldg(src + j);
    dst[2 * j]     = __floats2half2_rn(v.x, v.y);
    dst[2 * j + 1] = __floats2half2_rn(v.z, v.w);
}

// ---------------------------------------------------------------------------
// Kernel 1: QKV GEMM (fp16 mma, cp.async double-buffered).
// ---------------------------------------------------------------------------
__global__ __launch_bounds__(256) void qkv_gemm(const float* __restrict__ bias)
{
    __shared__ __align__(16) __half As[2][128][40];
    __shared__ __align__(16) __half Bs[2][128][40];

    const int tid = threadIdx.x, lane = tid & 31, w = tid >> 5;
    const int wm = w >> 1, wn = w & 1;
    const int m0 = blockIdx.y * 128, n0 = blockIdx.x * 128;

    float acc[2][8][4];
#pragma unroll
    for (int mt = 0; mt < 2; mt++)
#pragma unroll
        for (int nt = 0; nt < 8; nt++)
#pragma unroll
            for (int c = 0; c < 4; c++) acc[mt][nt][c] = 0.f;

    const int a_row  = wm * 32 + (lane & 15);
    const int a_colb = (lane >> 4) * 8;
    const int b_rowb = wn * 64 + (lane & 7) + ((lane >> 4) << 3);
    const int b_colb = ((lane >> 3) & 1) * 8;

    // chunk mapping for copies: 512 chunks of 16B per tile, 2 per thread
    const int r0 = tid >> 2,            c0 = (tid & 3) * 8;
    const int r1 = (tid + 256) >> 2,    c1 = c0;   // same col pattern

    auto copy_tiles = [&](int k0, int buf) {
        cp16(&As[buf][r0][c0], g_xh  + (size_t)(m0 + r0) * CH + k0 + c0);
        cp16(&As[buf][r1][c1], g_xh  + (size_t)(m0 + r1) * CH + k0 + c1);
        cp16(&Bs[buf][r0][c0], g_wqh + (size_t)(n0 + r0) * CH + k0 + c0);
        cp16(&Bs[buf][r1][c1], g_wqh + (size_t)(n0 + r1) * CH + k0 + c1);
    };

    copy_tiles(0, 0);
    CP_COMMIT();

    int buf = 0;
    for (int k = 0; k < CH / 32; k++) {
        if (k + 1 < CH / 32) {
            copy_tiles((k + 1) * 32, buf ^ 1);
            CP_COMMIT();
            CP_WAIT1();
        } else {
            CP_WAIT0();
        }
        __syncthreads();

#pragma unroll
        for (int ks = 0; ks < 2; ks++) {
            uint32_t aF[2][4];
#pragma unroll
            for (int mt = 0; mt < 2; mt++)
                ldm_x4(aF[mt], smem_u32(&As[buf][a_row + mt * 16][ks * 16 + a_colb]));
            uint32_t bF[8][2];
#pragma unroll
            for (int q = 0; q < 4; q++) {
                uint32_t r[4];
                ldm_x4(r, smem_u32(&Bs[buf][b_rowb + q * 16][ks * 16 + b_colb]));
                bF[2 * q][0] = r[0]; bF[2 * q][1] = r[1];
                bF[2 * q + 1][0] = r[2]; bF[2 * q + 1][1] = r[3];
            }
#pragma unroll
            for (int mt = 0; mt < 2; mt++)
#pragma unroll
                for (int nt = 0; nt < 8; nt++)
                    mma16816(acc[mt][nt], aF[mt], bF[nt]);
        }
        __syncthreads();
        buf ^= 1;
    }

    const int qr = lane >> 2, qc = (lane & 3) * 2;
#pragma unroll
    for (int mt = 0; mt < 2; mt++) {
#pragma unroll
        for (int nt = 0; nt < 8; nt++) {
            int jj = n0 + wn * 64 + nt * 8 + qc;
            float b0 = __ldg(&bias[jj]), b1 = __ldg(&bias[jj + 1]);
            int which = jj >> 9, h = (jj >> 5) & 15, dd = jj & 31;
#pragma unroll
            for (int rr = 0; rr < 2; rr++) {
                int m = m0 + wm * 32 + mt * 16 + qr + rr * 8;
                int b = m >> 10, n = m & 1023;
                float v0 = acc[mt][nt][rr * 2 + 0] + b0;
                float v1 = acc[mt][nt][rr * 2 + 1] + b1;
                if (which == 0) { v0 *= SCALE; v1 *= SCALE; }
                __half2 hv = __floats2half2_rn(v0, v1);
                size_t off = ((size_t)(b * NHEAD + h) * NTOK + n) * HD + dd;
                if (which == 0)      *(__half2*)&g_q[off] = hv;
                else if (which == 1) *(__half2*)&g_k[off] = hv;
                else                 *(__half2*)&g_v[off] = hv;
            }
        }
    }
}

// ---------------------------------------------------------------------------
// Kernel 2: flash attention, cp.async double-buffered K/V tiles.
// ---------------------------------------------------------------------------
__global__ __launch_bounds__(128) void attn_kernel(const float* __restrict__ rpb)
{
    const int bh = blockIdx.x;
    const int b  = bh >> 4, h = bh & 15;
    const int qbase = blockIdx.y * 64;
    const int tid = threadIdx.x, lane = tid & 31, w = tid >> 5;

    __shared__ float rpb_s[3969];
    __shared__ __align__(16) __half Qs[64][40];
    __shared__ __align__(16) __half Ks[2][64][40];
    __shared__ __align__(16) __half Vs[2][64][40];

    // K/V copy chunk mapping: 256 chunks of 16B per tensor tile, 2 per thread
    const int kr0 = tid >> 2,          kc0 = (tid & 3) * 8;
    const int kr1 = (tid + 128) >> 2,  kc1 = kc0;
    const __half* kbase = g_k + (size_t)bh * NTOK * HD;
    const __half* vbase = g_v + (size_t)bh * NTOK * HD;

    auto copy_kv = [&](int kt, int buf) {
        const __half* kg = kbase + kt * 64 * HD;
        const __half* vg = vbase + kt * 64 * HD;
        cp16(&Ks[buf][kr0][kc0], kg + kr0 * HD + kc0);
        cp16(&Ks[buf][kr1][kc1], kg + kr1 * HD + kc1);
        cp16(&Vs[buf][kr0][kc0], vg + kr0 * HD + kc0);
        cp16(&Vs[buf][kr1][kc1], vg + kr1 * HD + kc1);
    };

    copy_kv(0, 0);
    CP_COMMIT();

    for (int e = tid; e < 3969; e += 128)
        rpb_s[e] = __ldg(rpb + (size_t)h * 3969 + e);

    const __half* qg = g_q + ((size_t)bh * NTOK + qbase) * HD;
#pragma unroll
    for (int i = 0; i < 2; i++) {
        int e = tid + i * 128;
        int row = e >> 2, c8 = e & 3;
        *(uint4*)&Qs[row][c8 * 8] = *(const uint4*)(qg + row * HD + c8 * 8);
    }
    __syncthreads();

    uint32_t aQ[2][4];
#pragma unroll
    for (int ks = 0; ks < 2; ks++)
        ldm_x4(aQ[ks], smem_u32(&Qs[w * 16 + (lane & 15)][ks * 16 + (lane >> 4) * 8]));

    const int qr = lane >> 2, qc = (lane & 3) * 2;
    const int i1 = qbase + w * 16 + qr, i2 = i1 + 8;
    const int off1 = (31 - (i1 >> 5)) * 63 + (31 - (i1 & 31));
    const int off2 = (31 - (i2 >> 5)) * 63 + (31 - (i2 & 31));

    float m1 = -1e30f, m2 = -1e30f, l1 = 0.f, l2 = 0.f;
    float oacc[4][4];
#pragma unroll
    for (int i = 0; i < 4; i++)
#pragma unroll
        for (int c = 0; c < 4; c++) oacc[i][c] = 0.f;

    const int kb_row = (lane & 7) + ((lane >> 4) << 3);
    const int kb_col = ((lane >> 3) & 1) * 8;

    int buf = 0;
    for (int kt = 0; kt < 16; kt++) {
        if (kt + 1 < 16) {
            copy_kv(kt + 1, buf ^ 1);
            CP_COMMIT();
            CP_WAIT1();
        } else {
            CP_WAIT0();
        }
        __syncthreads();

        float sc[8][4];
#pragma unroll
        for (int nt = 0; nt < 8; nt++)
#pragma unroll
            for (int c = 0; c < 4; c++) sc[nt][c] = 0.f;

#pragma unroll
        for (int ks = 0; ks < 2; ks++) {
#pragma unroll
            for (int q = 0; q < 4; q++) {
                uint32_t r[4];
                ldm_x4(r, smem_u32(&Ks[buf][q * 16 + kb_row][ks * 16 + kb_col]));
                uint32_t b0[2] = { r[0], r[1] }, b1[2] = { r[2], r[3] };
                mma16816(sc[2 * q],     aQ[ks], b0);
                mma16816(sc[2 * q + 1], aQ[ks], b1);
            }
        }

        float tm1 = -1e30f, tm2 = -1e30f;
#pragma unroll
        for (int nt = 0; nt < 8; nt++) {
            int j0 = kt * 64 + nt * 8 + qc;
            int ja = j0 + 31 * (j0 >> 5);
            sc[nt][0] += rpb_s[off1 + ja];
            sc[nt][1] += rpb_s[off1 + ja + 1];
            sc[nt][2] += rpb_s[off2 + ja];
            sc[nt][3] += rpb_s[off2 + ja + 1];
            tm1 = fmaxf(tm1, fmaxf(sc[nt][0], sc[nt][1]));
            tm2 = fmaxf(tm2, fmaxf(sc[nt][2], sc[nt][3]));
        }
        tm1 = fmaxf(tm1, __shfl_xor_sync(0xffffffffu, tm1, 1));
        tm1 = fmaxf(tm1, __shfl_xor_sync(0xffffffffu, tm1, 2));
        tm2 = fmaxf(tm2, __shfl_xor_sync(0xffffffffu, tm2, 1));
        tm2 = fmaxf(tm2, __shfl_xor_sync(0xffffffffu, tm2, 2));

        float mn1 = fmaxf(m1, tm1), mn2 = fmaxf(m2, tm2);
        float cr1 = __expf(m1 - mn1), cr2 = __expf(m2 - mn2);
        l1 *= cr1; l2 *= cr2;
#pragma unroll
        for (int ntd = 0; ntd < 4; ntd++) {
            oacc[ntd][0] *= cr1; oacc[ntd][1] *= cr1;
            oacc[ntd][2] *= cr2; oacc[ntd][3] *= cr2;
        }
        float rs1 = 0.f, rs2 = 0.f;
#pragma unroll
        for (int nt = 0; nt < 8; nt++) {
            sc[nt][0] = __expf(sc[nt][0] - mn1); rs1 += sc[nt][0];
            sc[nt][1] = __expf(sc[nt][1] - mn1); rs1 += sc[nt][1];
            sc[nt][2] = __expf(sc[nt][2] - mn2); rs2 += sc[nt][2];
            sc[nt][3] = __expf(sc[nt][3] - mn2); rs2 += sc[nt][3];
        }
        rs1 += __shfl_xor_sync(0xffffffffu, rs1, 1);
        rs1 += __shfl_xor_sync(0xffffffffu, rs1, 2);
        rs2 += __shfl_xor_sync(0xffffffffu, rs2, 1);
        rs2 += __shfl_xor_sync(0xffffffffu, rs2, 2);
        l1 += rs1; l2 += rs2;
        m1 = mn1; m2 = mn2;

#pragma unroll
        for (int kk = 0; kk < 4; kk++) {
            uint32_t aP[4];
            aP[0] = pack_h2(sc[2 * kk][0],     sc[2 * kk][1]);
            aP[1] = pack_h2(sc[2 * kk][2],     sc[2 * kk][3]);
            aP[2] = pack_h2(sc[2 * kk + 1][0], sc[2 * kk + 1][1]);
            aP[3] = pack_h2(sc[2 * kk + 1][2], sc[2 * kk + 1][3]);
#pragma unroll
            for (int dp = 0; dp < 2; dp++) {
                uint32_t r[4];
                ldm_x4_t(r, smem_u32(&Vs[buf][kk * 16 + (lane & 15)][dp * 16 + (lane >> 4) * 8]));
                uint32_t b0[2] = { r[0], r[1] }, b1[2] = { r[2], r[3] };
                mma16816(oacc[2 * dp],     aP, b0);
                mma16816(oacc[2 * dp + 1], aP, b1);
            }
        }
        __syncthreads();
        buf ^= 1;
    }

    float inv1 = 1.f / l1, inv2 = 1.f / l2;
#pragma unroll
    for (int ntd = 0; ntd < 4; ntd++) {
        int d0 = ntd * 8 + qc;
        *(__half2*)&g_oh[((size_t)b * NTOK + i1) * CH + h * HD + d0] =
            __floats2half2_rn(oacc[ntd][0] * inv1, oacc[ntd][1] * inv1);
        *(__half2*)&g_oh[((size_t)b * NTOK + i2) * CH + h * HD + d0] =
            __floats2half2_rn(oacc[ntd][2] * inv2, oacc[ntd][3] * inv2);
    }
}

// ---------------------------------------------------------------------------
// Kernel 3: projection GEMM (fp16 mma, cp.async double-buffered).
// ---------------------------------------------------------------------------
__global__ __launch_bounds__(256) void proj_gemm(const float* __restrict__ bias,
                                                 float* __restrict__ out)
{
    __shared__ __align__(16) __half As[2][128][40];
    __shared__ __align__(16) __half Bs[2][128][40];

    const int tid = threadIdx.x, lane = tid & 31, w = tid >> 5;
    const int wm = w >> 1, wn = w & 1;
    const int m0 = blockIdx.y * 128, n0 = blockIdx.x * 128;

    float acc[2][8][4];
#pragma unroll
    for (int mt = 0; mt < 2; mt++)
#pragma unroll
        for (int nt = 0; nt < 8; nt++)
#pragma unroll
            for (int c = 0; c < 4; c++) acc[mt][nt][c] = 0.f;

    const int a_row  = wm * 32 + (lane & 15);
    const int a_colb = (lane >> 4) * 8;
    const int b_rowb = wn * 64 + (lane & 7) + ((lane >> 4) << 3);
    const int b_colb = ((lane >> 3) & 1) * 8;

    const int r0 = tid >> 2,         c0 = (tid & 3) * 8;
    const int r1 = (tid + 256) >> 2, c1 = c0;

    auto copy_tiles = [&](int k0, int buf) {
        cp16(&As[buf][r0][c0], g_oh  + (size_t)(m0 + r0) * CH + k0 + c0);
        cp16(&As[buf][r1][c1], g_oh  + (size_t)(m0 + r1) * CH + k0 + c1);
        cp16(&Bs[buf][r0][c0], g_pwh + (size_t)(n0 + r0) * CH + k0 + c0);
        cp16(&Bs[buf][r1][c1], g_pwh + (size_t)(n0 + r1) * CH + k0 + c1);
    };

    copy_tiles(0, 0);
    CP_COMMIT();

    int buf = 0;
    for (int k = 0; k < CH / 32; k++) {
        if (k + 1 < CH / 32) {
            copy_tiles((k + 1) * 32, buf ^ 1);
            CP_COMMIT();
            CP_WAIT1();
        } else {
            CP_WAIT0();
        }
        __syncthreads();

#pragma unroll
        for (int ks = 0; ks < 2; ks++) {
            uint32_t aF[2][4];
#pragma unroll
            for (int mt = 0; mt < 2; mt++)
                ldm_x4(aF[mt], smem_u32(&As[buf][a_row + mt * 16][ks * 16 + a_colb]));
            uint32_t bF[8][2];
#pragma unroll
            for (int q = 0; q < 4; q++) {
                uint32_t r[4];
                ldm_x4(r, smem_u32(&Bs[buf][b_rowb + q * 16][ks * 16 + b_colb]));
                bF[2 * q][0] = r[0]; bF[2 * q][1] = r[1];
                bF[2 * q + 1][0] = r[2]; bF[2 * q + 1][1] = r[3];
            }
#pragma unroll
            for (int mt = 0; mt < 2; mt++)
#pragma unroll
                for (int nt = 0; nt < 8; nt++)
                    mma16816(acc[mt][nt], aF[mt], bF[nt]);
        }
        __syncthreads();
        buf ^= 1;
    }

    const int qr = lane >> 2, qc = (lane & 3) * 2;
#pragma unroll
    for (int mt = 0; mt < 2; mt++) {
#pragma unroll
        for (int nt = 0; nt < 8; nt++) {
            int jj = n0 + wn * 64 + nt * 8 + qc;
            float b0 = __ldg(&bias[jj]), b1 = __ldg(&bias[jj + 1]);
#pragma unroll
            for (int rr = 0; rr < 2; rr++) {
                int m = m0 + wm * 32 + mt * 16 + qr + rr * 8;
                float2 v = make_float2(acc[mt][nt][rr * 2 + 0] + b0,
                                       acc[mt][nt][rr * 2 + 1] + b1);
                *(float2*)&out[(size_t)m * CH + jj] = v;
            }
        }
    }
}

// ---------------------------------------------------------------------------
extern "C" void kernel_launch(void* const* d_in, const int* in_sizes, int n_in,
                              void* d_out, int out_size)
{
    const float* x      = (const float*)d_in[0];
    const float* qkv_w  = (const float*)d_in[1];
    const float* qkv_b  = (const float*)d_in[2];
    const float* rpb    = (const float*)d_in[3];
    const float* proj_w = (const float*)d_in[4];
    const float* proj_b = (const float*)d_in[5];
    float* out = (float*)d_out;

    convert_all<<<(NX4 + NWQ4 + NWP4 + 255) / 256, 256>>>(
        (const float4*)x, (const float4*)qkv_w, (const float4*)proj_w);
    qkv_gemm<<<dim3(12, 64), 256>>>(qkv_b);
    attn_kernel<<<dim3(BATCH * NHEAD, NTOK / 64), 128>>>(rpb);
    proj_gemm<<<dim3(4, 64), 256>>>(proj_b, out);
}